// round 9
// baseline (speedup 1.0000x reference)
#include <cuda_runtime.h>
#include <cuda_bf16.h>
#include <cstdint>

// Problem constants: nw_out is [N=4, C=19, H=512, W=1024] float32.
#define NCH    19
#define NBAT   4
#define HH     512
#define WW     1024
#define HWP    (HH * WW)            // 524288 pixels per image-channel
#define NPIX   (NBAT * HWP)         // 2097152
#define IW_F   0.2f

// Tiling: each tile = 19 channels x 256 floats (256 pixels), 19456 bytes.
#define TILE_FLOATS   256
#define ROW_BYTES     (TILE_FLOATS * 4)          // 1024
#define TILE_BYTES    (NCH * ROW_BYTES)          // 19456
#define TILE_CHUNKS   (TILE_BYTES / 16)          // 1216 x 16B cp.async
#define TILES_PER_IMG (HWP / TILE_FLOATS)        // 2048
#define NTILES        (NBAT * TILES_PER_IMG)     // 8192
#define BLOCK_T       128                        // 1 float2 pair per thread per tile
#define GRID_BLOCKS   740                        // 5 CTAs/SM x 148 SMs (smem-limited)

// Scratch accumulators. Zeroed at module load; fused finalize re-zeroes them.
__device__ float        g_sum[NCH] = {};
__device__ unsigned int g_cnt[NCH] = {};
__device__ unsigned int g_done     = 0;

__device__ __forceinline__ unsigned int smem_u32(const void* p) {
    unsigned int a;
    asm("{ .reg .u64 t; cvta.to.shared.u64 t, %1; cvt.u32.u64 %0, t; }"
        : "=r"(a) : "l"(p));
    return a;
}

__global__ __launch_bounds__(BLOCK_T, 5) void msiw_kernel(const float* __restrict__ x,
                                                          float* __restrict__ out) {
    // Double-buffered tile staging + class accumulators (static smem < 48KB).
    __shared__ __align__(16) float buf[2][NCH * TILE_FLOATS];
    __shared__ float        s_sum[NCH];
    __shared__ unsigned int s_cnt[NCH];

    const int t = threadIdx.x;
    if (t < NCH) { s_sum[t] = 0.0f; s_cnt[t] = 0u; }
    __syncthreads();

    const unsigned int sbase = smem_u32(&buf[0][0]);

    // Issue one tile's 1216 x 16B cp.async into buffer bufi.
    auto issue_tile = [&](int tile, int bufi) {
        const int n  = tile / TILES_PER_IMG;
        const int x0 = (tile - n * TILES_PER_IMG) * TILE_FLOATS;
        const char* gb = (const char*)(x + (size_t)n * (NCH * HWP) + x0);
        const unsigned int sb = sbase + bufi * TILE_BYTES;
        for (int k = t; k < TILE_CHUNKS; k += BLOCK_T) {
            const int c   = k >> 6;                 // chunk row (channel)
            const int col = k & 63;                 // 16B column within row
            const unsigned int  dst = sb + c * ROW_BYTES + col * 16;
            const char*         src = gb + (size_t)c * (HWP * 4) + col * 16;
            asm volatile("cp.async.cg.shared.global [%0], [%1], 16;"
                         :: "r"(dst), "l"(src));
        }
        asm volatile("cp.async.commit_group;");
    };

    int tile = blockIdx.x;
    issue_tile(tile, 0);                            // prologue (740 < 8192 always)
    int parity = 0;

    for (; tile < NTILES; tile += GRID_BLOCKS) {
        const int next = tile + GRID_BLOCKS;
        if (next < NTILES) {
            issue_tile(next, parity ^ 1);
            asm volatile("cp.async.wait_group 1;"); // current tile complete
        } else {
            asm volatile("cp.async.wait_group 0;");
        }
        __syncthreads();

        // ---- compute: one float2 pair per thread from smem ----
        const float* bp = &buf[parity][0];
        float2 v[NCH];
#pragma unroll
        for (int c = 0; c < NCH; c++) {
            v[c] = *(const float2*)(bp + c * TILE_FLOATS + 2 * t);  // LDS.64, conflict-free
        }

        // Per-component argmax (strict > = first-max semantics).
        float mx = v[0].x, my = v[0].y;
        int ix = 0, iy = 0;
#pragma unroll
        for (int c = 1; c < NCH; c++) {
            if (v[c].x > mx) { mx = v[c].x; ix = c; }
            if (v[c].y > my) { my = v[c].y; iy = c; }
        }

        // s1 = sum e^(v-m), s2 = sum e^2(v-m), packed f32x2 (R8-proven).
        unsigned long long m2, s1p, s2p;
        asm("mov.b64 %0, {%1, %2};" : "=l"(m2) : "f"(mx), "f"(my));
        asm("mov.b64 %0, {%1, %2};" : "=l"(s1p) : "f"(0.0f), "f"(0.0f));
        asm("mov.b64 %0, {%1, %2};" : "=l"(s2p) : "f"(0.0f), "f"(0.0f));
#pragma unroll
        for (int c = 0; c < NCH; c++) {
            unsigned long long v2c, d2, e2;
            asm("mov.b64 %0, {%1, %2};" : "=l"(v2c) : "f"(v[c].x), "f"(v[c].y));
            asm("sub.rn.f32x2 %0, %1, %2;" : "=l"(d2) : "l"(v2c), "l"(m2));
            float dx, dy;
            asm("mov.b64 {%0, %1}, %2;" : "=f"(dx), "=f"(dy) : "l"(d2));
            float ex = __expf(dx);
            float ey = __expf(dy);
            asm("mov.b64 %0, {%1, %2};" : "=l"(e2) : "f"(ex), "f"(ey));
            asm("add.rn.f32x2 %0, %1, %2;" : "=l"(s1p) : "l"(s1p), "l"(e2));
            asm("fma.rn.f32x2 %0, %1, %2, %3;" : "=l"(s2p) : "l"(e2), "l"(e2), "l"(s2p));
        }
        float s1x, s1y, s2x, s2y;
        asm("mov.b64 {%0, %1}, %2;" : "=f"(s1x), "=f"(s1y) : "l"(s1p));
        asm("mov.b64 {%0, %1}, %2;" : "=f"(s2x), "=f"(s2y) : "l"(s2p));

        atomicAdd(&s_sum[ix], __fdividef(s2x, s1x * s1x));
        atomicAdd(&s_sum[iy], __fdividef(s2y, s1y * s1y));
        atomicAdd(&s_cnt[ix], 1u);
        atomicAdd(&s_cnt[iy], 1u);

        __syncthreads();   // all reads of buf[parity] done before it is re-filled
        parity ^= 1;
    }

    if (t < NCH) {
        atomicAdd(&g_sum[t], s_sum[t]);
        atomicAdd(&g_cnt[t], s_cnt[t]);
    }

    // ---- fused finalize: last block does the 19-term reduction ----
    __threadfence();
    __shared__ unsigned int s_last;
    if (t == 0) {
        unsigned int ticket = atomicAdd(&g_done, 1u);
        s_last = (ticket == GRID_BLOCKS - 1) ? 1u : 0u;
    }
    __syncthreads();
    if (s_last && t < 32) {
        int c = t;
        float partial = 0.0f;
        if (c < NCH) {
            float cnt   = (float)g_cnt[c];
            float scale = powf((float)NPIX, 1.0f - IW_F);        // Np^0.8
            float den   = fmaxf(powf(cnt, IW_F) * scale, 1.0f);  // max(hist^0.2*Np^0.8, 1)
            partial = g_sum[c] / den;
            g_sum[c] = 0.0f;                                     // reset for next replay
            g_cnt[c] = 0u;
        }
#pragma unroll
        for (int o = 16; o > 0; o >>= 1)
            partial += __shfl_down_sync(0xffffffffu, partial, o);
        if (c == 0) {
            out[0] = -partial / (float)(NBAT * NCH);
            g_done = 0;                                          // reset ticket
        }
    }
}

extern "C" void kernel_launch(void* const* d_in, const int* in_sizes, int n_in,
                              void* d_out, int out_size) {
    (void)in_sizes; (void)n_in; (void)out_size;
    const float* x = (const float*)d_in[0];
    float* out = (float*)d_out;

    // Single launch: 740 CTAs x 128 threads, 5 CTAs/SM (38.9KB smem each),
    // cp.async double-buffered tiles, fused last-block finalize.
    msiw_kernel<<<GRID_BLOCKS, BLOCK_T>>>(x, out);
}